// round 14
// baseline (speedup 1.0000x reference)
#include <cuda_runtime.h>
#include <cuda_bf16.h>
#include <math.h>

// Problem constants
#define BATCH   32
#define S_NEW   8
#define S_CACHE 4096
#define S_TOT   4104            // 4096 + 8
#define DIM     1024
#define M_ROWS  (BATCH * S_NEW) // 256
#define SPLITS  16
#define CHUNK   ((S_TOT + SPLITS - 1) / SPLITS)   // 257
#define NSLICE  (2 * SPLITS)                      // 32 partial slices
#define KSPLIT  4                                 // proj split-K factor

// Scratch (allocation-free rule: __device__ globals)
__device__ float g_q[M_ROWS * DIM];                   // 1 MB   q_new
__device__ float g_scores[M_ROWS * S_TOT];            // ~4.2 MB scores -> probs
__device__ float g_part[NSLICE * M_ROWS * DIM];       // 32 MB  split-K partials
__device__ float g_ppart[3 * KSPLIT * M_ROWS * DIM];  // 12.6 MB proj partials

// ---------------------------------------------------------------------------
// Kernel 1: split-K projections. Partial C for K chunk kc -> g_ppart.
// grid (16, 4, 12): blockIdx.z = z*KSPLIT + kc, z in {Q,K,V}.
// ---------------------------------------------------------------------------
__global__ void __launch_bounds__(256)
proj_kernel(const float* __restrict__ x,
            const float* __restrict__ Wq,
            const float* __restrict__ Wk,
            const float* __restrict__ Wv)
{
    const int z2 = blockIdx.z;
    const int z  = z2 >> 2;          // 0=Q,1=K,2=V
    const int kc = z2 & (KSPLIT - 1);
    const float* W = (z == 0) ? Wq : (z == 1) ? Wk : Wv;

    __shared__ float xs[64][17];
    __shared__ float ws[16][64];

    const int tid = threadIdx.x;
    const int tx = tid & 15, ty = tid >> 4;
    const int m0 = blockIdx.y * 64, n0 = blockIdx.x * 64;
    const int kbeg = kc * (DIM / KSPLIT), kend = kbeg + DIM / KSPLIT;

    float acc[4][4] = {};

    for (int k0 = kbeg; k0 < kend; k0 += 16) {
        {   // x tile 64x16
            int r = tid >> 2;
            int c = (tid & 3) * 4;
            float4 v = *(const float4*)(x + (size_t)(m0 + r) * DIM + k0 + c);
            xs[r][c] = v.x; xs[r][c + 1] = v.y; xs[r][c + 2] = v.z; xs[r][c + 3] = v.w;
        }
        {   // W tile 16x64
            int r = tid >> 4;
            int c = (tid & 15) * 4;
            *(float4*)&ws[r][c] = *(const float4*)(W + (size_t)(k0 + r) * DIM + n0 + c);
        }
        __syncthreads();
        #pragma unroll
        for (int kk = 0; kk < 16; kk++) {
            float a[4];
            #pragma unroll
            for (int i = 0; i < 4; i++) a[i] = xs[ty * 4 + i][kk];
            float4 bb = *(float4*)&ws[kk][tx * 4];
            #pragma unroll
            for (int i = 0; i < 4; i++) {
                acc[i][0] += a[i] * bb.x;
                acc[i][1] += a[i] * bb.y;
                acc[i][2] += a[i] * bb.z;
                acc[i][3] += a[i] * bb.w;
            }
        }
        __syncthreads();
    }

    float* dst = g_ppart + (size_t)z2 * M_ROWS * DIM;
    #pragma unroll
    for (int i = 0; i < 4; i++) {
        int m = m0 + ty * 4 + i;
        float4 v;
        v.x = acc[i][0]; v.y = acc[i][1]; v.z = acc[i][2]; v.w = acc[i][3];
        *(float4*)(dst + (size_t)m * DIM + n0 + tx * 4) = v;
    }
}

// ---------------------------------------------------------------------------
// Kernel 1b: proj combine. Sums KSPLIT partials + bias; routes to
// g_q (z=0) or keys/values tails (z=1,2). grid 768 x 256 (float4 jobs).
// ---------------------------------------------------------------------------
__global__ void __launch_bounds__(256)
pcombine_kernel(const float* __restrict__ bq,
                const float* __restrict__ bk,
                const float* __restrict__ bv,
                float* __restrict__ keys, float* __restrict__ values)
{
    const int idx = blockIdx.x * 256 + threadIdx.x;    // float4 job
    const int z   = idx >> 16;                          // 65536 f4 per z
    const int r   = idx & 65535;
    const int m   = r >> 8;
    const int n   = (r & 255) * 4;

    const float4* p = (const float4*)(g_ppart + (size_t)z * KSPLIT * M_ROWS * DIM
                                      + (size_t)m * DIM + n);
    float4 a = {0.f, 0.f, 0.f, 0.f};
    #pragma unroll
    for (int kc = 0; kc < KSPLIT; kc++) {
        float4 v = p[(size_t)kc * (M_ROWS * DIM / 4)];
        a.x += v.x; a.y += v.y; a.z += v.z; a.w += v.w;
    }
    const float* bias = (z == 0) ? bq : (z == 1) ? bk : bv;
    float4 bb = *(const float4*)(bias + n);
    a.x += bb.x; a.y += bb.y; a.z += bb.z; a.w += bb.w;

    if (z == 0) {
        *(float4*)(g_q + (size_t)m * DIM + n) = a;
    } else {
        int b = m >> 3, s = m & 7;
        float* dst = (z == 1) ? keys : values;
        *(float4*)(dst + (size_t)b * S_TOT * DIM + (size_t)(S_CACHE + s) * DIM + n) = a;
    }
}

// ---------------------------------------------------------------------------
// Dummy kernel: keeps scores_kernel at the profiled launch index.
// ---------------------------------------------------------------------------
__global__ void slot_kernel() {}

// ---------------------------------------------------------------------------
// Kernel 2: fused key-cache copy + scores (v5: occupancy-first).
// __launch_bounds__(512, 2) caps regs at 64 -> 2 CTAs/SM (50% occ).
// No software prefetch: latency hidden by 2x resident warps (TLP).
// grid (129, BATCH); blocks 0..127 cache rows, block 128 tail rows.
// ---------------------------------------------------------------------------
__global__ void __launch_bounds__(512, 2)
scores_kernel(const float* __restrict__ key_cache,
              float* __restrict__ keys)
{
    const int b    = blockIdx.y;
    const int tid  = threadIdx.x;
    const int warp = tid >> 5, lane = tid & 31;

    __shared__ float4 qs4[S_NEW * 256];   // 8 queries x 1024 floats = 32 KB
    {
        const float4* qsrc = (const float4*)(g_q + (size_t)b * S_NEW * DIM);
        #pragma unroll
        for (int i = 0; i < 4; i++) qs4[tid + i * 512] = qsrc[tid + i * 512];
    }
    __syncthreads();

    float acc0[S_NEW] = {}, acc1[S_NEW] = {};
    int row0;

    if (blockIdx.x < 128) {
        row0 = blockIdx.x * 32 + warp * 2;
        const float4* s0 = (const float4*)(key_cache + ((size_t)b * S_CACHE + row0) * DIM) + lane;
        const float4* s1 = s0 + DIM / 4;
        float4* d0 = (float4*)(keys + ((size_t)b * S_TOT + row0) * DIM) + lane;
        float4* d1 = d0 + DIM / 4;

        #pragma unroll
        for (int it = 0; it < 8; it++) {
            float4 a0 = __ldcs(s0 + it * 32);
            float4 a1 = __ldcs(s1 + it * 32);
            __stcs(d0 + it * 32, a0);
            __stcs(d1 + it * 32, a1);
            #pragma unroll
            for (int q = 0; q < S_NEW; q++) {
                float4 qv = qs4[q * 256 + it * 32 + lane];
                acc0[q] += a0.x * qv.x + a0.y * qv.y + a0.z * qv.z + a0.w * qv.w;
                acc1[q] += a1.x * qv.x + a1.y * qv.y + a1.z * qv.z + a1.w * qv.w;
            }
        }
    } else {
        if (warp >= 4) return;
        row0 = S_CACHE + warp * 2;
        const float* s0 = keys + ((size_t)b * S_TOT + row0) * DIM + lane * 4;
        const float* s1 = s0 + DIM;
        #pragma unroll
        for (int it = 0; it < 8; it++) {
            float4 a0 = *(const float4*)(s0 + it * 128);
            float4 a1 = *(const float4*)(s1 + it * 128);
            #pragma unroll
            for (int q = 0; q < S_NEW; q++) {
                float4 qv = qs4[q * 256 + it * 32 + lane];
                acc0[q] += a0.x * qv.x + a0.y * qv.y + a0.z * qv.z + a0.w * qv.w;
                acc1[q] += a1.x * qv.x + a1.y * qv.y + a1.z * qv.z + a1.w * qv.w;
            }
        }
    }

    #pragma unroll
    for (int q = 0; q < S_NEW; q++) {
        float v0 = acc0[q], v1 = acc1[q];
        #pragma unroll
        for (int off = 16; off; off >>= 1) {
            v0 += __shfl_down_sync(0xFFFFFFFFu, v0, off);
            v1 += __shfl_down_sync(0xFFFFFFFFu, v1, off);
        }
        if (lane == 0) {
            g_scores[((size_t)b * S_NEW + q) * S_TOT + row0]     = v0 * 0.03125f;
            g_scores[((size_t)b * S_NEW + q) * S_TOT + row0 + 1] = v1 * 0.03125f;
        }
    }
}

// ---------------------------------------------------------------------------
// Kernel 3: softmax, register-resident (1 read + 1 write per element).
// ---------------------------------------------------------------------------
#define SM_PER_T 17   // 256*17 = 4352 >= 4104
__global__ void __launch_bounds__(256)
softmax_kernel()
{
    float* p = g_scores + (size_t)blockIdx.x * S_TOT;
    const int tid = threadIdx.x;
    __shared__ float red[256];

    float val[SM_PER_T];
    float m = -1e30f;
    #pragma unroll
    for (int i = 0; i < SM_PER_T; i++) {
        int idx = tid + i * 256;
        val[i] = (idx < S_TOT) ? p[idx] : -1e30f;
        m = fmaxf(m, val[i]);
    }
    red[tid] = m; __syncthreads();
    for (int s = 128; s; s >>= 1) {
        if (tid < s) red[tid] = fmaxf(red[tid], red[tid + s]);
        __syncthreads();
    }
    m = red[0];
    __syncthreads();

    float sum = 0.f;
    #pragma unroll
    for (int i = 0; i < SM_PER_T; i++) {
        val[i] = __expf(val[i] - m);
        sum += val[i];
    }
    red[tid] = sum; __syncthreads();
    for (int s = 128; s; s >>= 1) {
        if (tid < s) red[tid] += red[tid + s];
        __syncthreads();
    }
    const float inv = 1.0f / red[0];
    #pragma unroll
    for (int i = 0; i < SM_PER_T; i++) {
        int idx = tid + i * 256;
        if (idx < S_TOT) p[idx] = val[i] * inv;
    }
}

// ---------------------------------------------------------------------------
// Kernel 4: fused value-cache copy + split-K probs @ V. (unchanged, 75% DRAM)
// ---------------------------------------------------------------------------
__global__ void __launch_bounds__(512)
out_kernel(const float* __restrict__ value_cache,
           float* __restrict__ values)
{
    const int b    = blockIdx.x;
    const int z    = blockIdx.y;
    const int tid  = threadIdx.x;
    const int grp  = tid >> 8;
    const int col  = (tid & 255) * 4;

    const int s_beg = z * CHUNK;
    const int s_end = (s_beg + CHUNK < S_TOT) ? s_beg + CHUNK : S_TOT;
    const int s_mid = (s_end < S_CACHE) ? s_end : ((s_beg > S_CACHE) ? s_beg : S_CACHE);

    __shared__ float ps[S_NEW][CHUNK];
    {
        const float* probs = g_scores + (size_t)b * S_NEW * S_TOT;
        const int n = s_end - s_beg;
        for (int i = tid; i < S_NEW * n; i += 512) {
            int q = i / n, s = i - q * n;
            ps[q][s] = probs[(size_t)q * S_TOT + s_beg + s];
        }
    }
    __syncthreads();

    float acc[S_NEW][4] = {};

    const float* vsrc = value_cache + (size_t)b * S_CACHE * DIM + col;
    float*       vdst = values      + (size_t)b * S_TOT   * DIM + col;

    #pragma unroll 2
    for (int s = s_beg + grp; s < s_mid; s += 2) {
        float4 vv = *(const float4*)(vsrc + (size_t)s * DIM);
        *(float4*)(vdst + (size_t)s * DIM) = vv;
        #pragma unroll
        for (int q = 0; q < S_NEW; q++) {
            float pq = ps[q][s - s_beg];
            acc[q][0] += pq * vv.x;
            acc[q][1] += pq * vv.y;
            acc[q][2] += pq * vv.z;
            acc[q][3] += pq * vv.w;
        }
    }
    for (int s = s_mid; s < s_end; s++) {
        if (((s - s_beg) & 1) != grp) continue;
        float4 vv = *(const float4*)(vdst + (size_t)s * DIM);
        #pragma unroll
        for (int q = 0; q < S_NEW; q++) {
            float pq = ps[q][s - s_beg];
            acc[q][0] += pq * vv.x;
            acc[q][1] += pq * vv.y;
            acc[q][2] += pq * vv.z;
            acc[q][3] += pq * vv.w;
        }
    }

    float* pbase = g_part + (size_t)(z * 2 + grp) * M_ROWS * DIM
                          + (size_t)b * S_NEW * DIM + col;
    #pragma unroll
    for (int q = 0; q < S_NEW; q++)
        *(float4*)(pbase + (size_t)q * DIM) = *(float4*)acc[q];
}

// ---------------------------------------------------------------------------
// Kernel 5: deterministic split-K combine for attention output.
// ---------------------------------------------------------------------------
__global__ void combine_kernel(float* __restrict__ out)
{
    const int idx = blockIdx.x * blockDim.x + threadIdx.x;
    const float4* p = (const float4*)g_part + idx;
    float4 a = {0.f, 0.f, 0.f, 0.f};
    #pragma unroll
    for (int z = 0; z < NSLICE; z++) {
        float4 v = p[(size_t)z * (M_ROWS * DIM / 4)];
        a.x += v.x; a.y += v.y; a.z += v.z; a.w += v.w;
    }
    ((float4*)out)[idx] = a;
}

// ---------------------------------------------------------------------------
extern "C" void kernel_launch(void* const* d_in, const int* in_sizes, int n_in,
                              void* d_out, int out_size)
{
    const float* input       = (const float*)d_in[0];
    const float* key_cache   = (const float*)d_in[1];
    const float* value_cache = (const float*)d_in[2];
    const float* Wk          = (const float*)d_in[3];
    const float* bk          = (const float*)d_in[4];
    const float* Wv          = (const float*)d_in[5];
    const float* bv          = (const float*)d_in[6];
    const float* Wq          = (const float*)d_in[7];
    const float* bq          = (const float*)d_in[8];

    float* out    = (float*)d_out;                                // [B, S_NEW, D]
    float* keys   = out + (size_t)BATCH * S_NEW * DIM;            // [B, S_TOT, D]
    float* values = keys + (size_t)BATCH * S_TOT * DIM;           // [B, S_TOT, D]

    // 1) split-K projections + combine (bias, routing to q / tails)   [0][1]
    proj_kernel<<<dim3(16, 4, 3 * KSPLIT), 256>>>(input, Wq, Wk, Wv);
    pcombine_kernel<<<768, 256>>>(bq, bk, bv, keys, values);

    // slot shim so scores_kernel is launch #3 (profiled slot)         [2]
    slot_kernel<<<1, 32>>>();

    // 2) fused key copy + scores                                      [3]
    scores_kernel<<<dim3(129, BATCH), 512>>>(key_cache, keys);

    // 3) softmax (register-resident)                                  [4]
    softmax_kernel<<<M_ROWS, 256>>>();

    // 4) fused value copy + split-K probs @ V                         [5]
    out_kernel<<<dim3(BATCH, SPLITS), 512>>>(value_cache, values);

    // 5) deterministic combine of split-K partials                    [6]
    combine_kernel<<<(M_ROWS * DIM / 4) / 256, 256>>>(out);
}

// round 16
// speedup vs baseline: 1.0009x; 1.0009x over previous
#include <cuda_runtime.h>
#include <cuda_bf16.h>
#include <math.h>

// Problem constants
#define BATCH   32
#define S_NEW   8
#define S_CACHE 4096
#define S_TOT   4104            // 4096 + 8
#define DIM     1024
#define M_ROWS  (BATCH * S_NEW) // 256
#define SPLITS  16
#define CHUNK   ((S_TOT + SPLITS - 1) / SPLITS)   // 257
#define NSLICE  (2 * SPLITS)                      // 32 partial slices
#define KSPLIT  4                                 // proj split-K factor

// Scratch (allocation-free rule: __device__ globals)
__device__ float g_q[M_ROWS * DIM];                   // 1 MB   q_new
__device__ float g_scores[M_ROWS * S_TOT];            // ~4.2 MB scores -> probs
__device__ float g_part[NSLICE * M_ROWS * DIM];       // 32 MB  split-K partials
__device__ float g_ppart[3 * KSPLIT * M_ROWS * DIM];  // 12.6 MB proj partials

// ---------------------------------------------------------------------------
// Kernel 1: split-K projections. Partial C for K chunk kc -> g_ppart.
// grid (16, 4, 12): blockIdx.z = z*KSPLIT + kc, z in {Q,K,V}.
// ---------------------------------------------------------------------------
__global__ void __launch_bounds__(256)
proj_kernel(const float* __restrict__ x,
            const float* __restrict__ Wq,
            const float* __restrict__ Wk,
            const float* __restrict__ Wv)
{
    const int z2 = blockIdx.z;
    const int z  = z2 >> 2;          // 0=Q,1=K,2=V
    const int kc = z2 & (KSPLIT - 1);
    const float* W = (z == 0) ? Wq : (z == 1) ? Wk : Wv;

    __shared__ float xs[64][17];
    __shared__ float ws[16][64];

    const int tid = threadIdx.x;
    const int tx = tid & 15, ty = tid >> 4;
    const int m0 = blockIdx.y * 64, n0 = blockIdx.x * 64;
    const int kbeg = kc * (DIM / KSPLIT), kend = kbeg + DIM / KSPLIT;

    float acc[4][4] = {};

    for (int k0 = kbeg; k0 < kend; k0 += 16) {
        {   // x tile 64x16
            int r = tid >> 2;
            int c = (tid & 3) * 4;
            float4 v = *(const float4*)(x + (size_t)(m0 + r) * DIM + k0 + c);
            xs[r][c] = v.x; xs[r][c + 1] = v.y; xs[r][c + 2] = v.z; xs[r][c + 3] = v.w;
        }
        {   // W tile 16x64
            int r = tid >> 4;
            int c = (tid & 15) * 4;
            *(float4*)&ws[r][c] = *(const float4*)(W + (size_t)(k0 + r) * DIM + n0 + c);
        }
        __syncthreads();
        #pragma unroll
        for (int kk = 0; kk < 16; kk++) {
            float a[4];
            #pragma unroll
            for (int i = 0; i < 4; i++) a[i] = xs[ty * 4 + i][kk];
            float4 bb = *(float4*)&ws[kk][tx * 4];
            #pragma unroll
            for (int i = 0; i < 4; i++) {
                acc[i][0] += a[i] * bb.x;
                acc[i][1] += a[i] * bb.y;
                acc[i][2] += a[i] * bb.z;
                acc[i][3] += a[i] * bb.w;
            }
        }
        __syncthreads();
    }

    float* dst = g_ppart + (size_t)z2 * M_ROWS * DIM;
    #pragma unroll
    for (int i = 0; i < 4; i++) {
        int m = m0 + ty * 4 + i;
        float4 v;
        v.x = acc[i][0]; v.y = acc[i][1]; v.z = acc[i][2]; v.w = acc[i][3];
        *(float4*)(dst + (size_t)m * DIM + n0 + tx * 4) = v;
    }
}

// ---------------------------------------------------------------------------
// Kernel 1b: proj combine. Sums KSPLIT partials + bias; routes to
// g_q (z=0) or keys/values tails (z=1,2). grid 768 x 256 (float4 jobs).
// ---------------------------------------------------------------------------
__global__ void __launch_bounds__(256)
pcombine_kernel(const float* __restrict__ bq,
                const float* __restrict__ bk,
                const float* __restrict__ bv,
                float* __restrict__ keys, float* __restrict__ values)
{
    const int idx = blockIdx.x * 256 + threadIdx.x;    // float4 job
    const int z   = idx >> 16;                          // 65536 f4 per z
    const int r   = idx & 65535;
    const int m   = r >> 8;
    const int n   = (r & 255) * 4;

    const float4* p = (const float4*)(g_ppart + (size_t)z * KSPLIT * M_ROWS * DIM
                                      + (size_t)m * DIM + n);
    float4 a = {0.f, 0.f, 0.f, 0.f};
    #pragma unroll
    for (int kc = 0; kc < KSPLIT; kc++) {
        float4 v = p[(size_t)kc * (M_ROWS * DIM / 4)];
        a.x += v.x; a.y += v.y; a.z += v.z; a.w += v.w;
    }
    const float* bias = (z == 0) ? bq : (z == 1) ? bk : bv;
    float4 bb = *(const float4*)(bias + n);
    a.x += bb.x; a.y += bb.y; a.z += bb.z; a.w += bb.w;

    if (z == 0) {
        *(float4*)(g_q + (size_t)m * DIM + n) = a;
    } else {
        int b = m >> 3, s = m & 7;
        float* dst = (z == 1) ? keys : values;
        *(float4*)(dst + (size_t)b * S_TOT * DIM + (size_t)(S_CACHE + s) * DIM + n) = a;
    }
}

// ---------------------------------------------------------------------------
// Dummy kernel: keeps scores_kernel at the profiled launch index.
// ---------------------------------------------------------------------------
__global__ void slot_kernel() {}

// ---------------------------------------------------------------------------
// Kernel 2: fused key-cache copy + scores (v5: occupancy-first).
// __launch_bounds__(512, 2) caps regs at 64 -> 2 CTAs/SM (50% occ).
// No software prefetch: latency hidden by 2x resident warps (TLP).
// grid (129, BATCH); blocks 0..127 cache rows, block 128 tail rows.
// ---------------------------------------------------------------------------
__global__ void __launch_bounds__(512, 2)
scores_kernel(const float* __restrict__ key_cache,
              float* __restrict__ keys)
{
    const int b    = blockIdx.y;
    const int tid  = threadIdx.x;
    const int warp = tid >> 5, lane = tid & 31;

    __shared__ float4 qs4[S_NEW * 256];   // 8 queries x 1024 floats = 32 KB
    {
        const float4* qsrc = (const float4*)(g_q + (size_t)b * S_NEW * DIM);
        #pragma unroll
        for (int i = 0; i < 4; i++) qs4[tid + i * 512] = qsrc[tid + i * 512];
    }
    __syncthreads();

    float acc0[S_NEW] = {}, acc1[S_NEW] = {};
    int row0;

    if (blockIdx.x < 128) {
        row0 = blockIdx.x * 32 + warp * 2;
        const float4* s0 = (const float4*)(key_cache + ((size_t)b * S_CACHE + row0) * DIM) + lane;
        const float4* s1 = s0 + DIM / 4;
        float4* d0 = (float4*)(keys + ((size_t)b * S_TOT + row0) * DIM) + lane;
        float4* d1 = d0 + DIM / 4;

        #pragma unroll
        for (int it = 0; it < 8; it++) {
            float4 a0 = __ldcs(s0 + it * 32);
            float4 a1 = __ldcs(s1 + it * 32);
            __stcs(d0 + it * 32, a0);
            __stcs(d1 + it * 32, a1);
            #pragma unroll
            for (int q = 0; q < S_NEW; q++) {
                float4 qv = qs4[q * 256 + it * 32 + lane];
                acc0[q] += a0.x * qv.x + a0.y * qv.y + a0.z * qv.z + a0.w * qv.w;
                acc1[q] += a1.x * qv.x + a1.y * qv.y + a1.z * qv.z + a1.w * qv.w;
            }
        }
    } else {
        if (warp >= 4) return;
        row0 = S_CACHE + warp * 2;
        const float* s0 = keys + ((size_t)b * S_TOT + row0) * DIM + lane * 4;
        const float* s1 = s0 + DIM;
        #pragma unroll
        for (int it = 0; it < 8; it++) {
            float4 a0 = *(const float4*)(s0 + it * 128);
            float4 a1 = *(const float4*)(s1 + it * 128);
            #pragma unroll
            for (int q = 0; q < S_NEW; q++) {
                float4 qv = qs4[q * 256 + it * 32 + lane];
                acc0[q] += a0.x * qv.x + a0.y * qv.y + a0.z * qv.z + a0.w * qv.w;
                acc1[q] += a1.x * qv.x + a1.y * qv.y + a1.z * qv.z + a1.w * qv.w;
            }
        }
    }

    #pragma unroll
    for (int q = 0; q < S_NEW; q++) {
        float v0 = acc0[q], v1 = acc1[q];
        #pragma unroll
        for (int off = 16; off; off >>= 1) {
            v0 += __shfl_down_sync(0xFFFFFFFFu, v0, off);
            v1 += __shfl_down_sync(0xFFFFFFFFu, v1, off);
        }
        if (lane == 0) {
            g_scores[((size_t)b * S_NEW + q) * S_TOT + row0]     = v0 * 0.03125f;
            g_scores[((size_t)b * S_NEW + q) * S_TOT + row0 + 1] = v1 * 0.03125f;
        }
    }
}

// ---------------------------------------------------------------------------
// Kernel 3: softmax, register-resident (1 read + 1 write per element).
// ---------------------------------------------------------------------------
#define SM_PER_T 17   // 256*17 = 4352 >= 4104
__global__ void __launch_bounds__(256)
softmax_kernel()
{
    float* p = g_scores + (size_t)blockIdx.x * S_TOT;
    const int tid = threadIdx.x;
    __shared__ float red[256];

    float val[SM_PER_T];
    float m = -1e30f;
    #pragma unroll
    for (int i = 0; i < SM_PER_T; i++) {
        int idx = tid + i * 256;
        val[i] = (idx < S_TOT) ? p[idx] : -1e30f;
        m = fmaxf(m, val[i]);
    }
    red[tid] = m; __syncthreads();
    for (int s = 128; s; s >>= 1) {
        if (tid < s) red[tid] = fmaxf(red[tid], red[tid + s]);
        __syncthreads();
    }
    m = red[0];
    __syncthreads();

    float sum = 0.f;
    #pragma unroll
    for (int i = 0; i < SM_PER_T; i++) {
        val[i] = __expf(val[i] - m);
        sum += val[i];
    }
    red[tid] = sum; __syncthreads();
    for (int s = 128; s; s >>= 1) {
        if (tid < s) red[tid] += red[tid + s];
        __syncthreads();
    }
    const float inv = 1.0f / red[0];
    #pragma unroll
    for (int i = 0; i < SM_PER_T; i++) {
        int idx = tid + i * 256;
        if (idx < S_TOT) p[idx] = val[i] * inv;
    }
}

// ---------------------------------------------------------------------------
// Kernel 4: fused value-cache copy + split-K probs @ V. (unchanged, 75% DRAM)
// ---------------------------------------------------------------------------
__global__ void __launch_bounds__(512)
out_kernel(const float* __restrict__ value_cache,
           float* __restrict__ values)
{
    const int b    = blockIdx.x;
    const int z    = blockIdx.y;
    const int tid  = threadIdx.x;
    const int grp  = tid >> 8;
    const int col  = (tid & 255) * 4;

    const int s_beg = z * CHUNK;
    const int s_end = (s_beg + CHUNK < S_TOT) ? s_beg + CHUNK : S_TOT;
    const int s_mid = (s_end < S_CACHE) ? s_end : ((s_beg > S_CACHE) ? s_beg : S_CACHE);

    __shared__ float ps[S_NEW][CHUNK];
    {
        const float* probs = g_scores + (size_t)b * S_NEW * S_TOT;
        const int n = s_end - s_beg;
        for (int i = tid; i < S_NEW * n; i += 512) {
            int q = i / n, s = i - q * n;
            ps[q][s] = probs[(size_t)q * S_TOT + s_beg + s];
        }
    }
    __syncthreads();

    float acc[S_NEW][4] = {};

    const float* vsrc = value_cache + (size_t)b * S_CACHE * DIM + col;
    float*       vdst = values      + (size_t)b * S_TOT   * DIM + col;

    #pragma unroll 2
    for (int s = s_beg + grp; s < s_mid; s += 2) {
        float4 vv = *(const float4*)(vsrc + (size_t)s * DIM);
        *(float4*)(vdst + (size_t)s * DIM) = vv;
        #pragma unroll
        for (int q = 0; q < S_NEW; q++) {
            float pq = ps[q][s - s_beg];
            acc[q][0] += pq * vv.x;
            acc[q][1] += pq * vv.y;
            acc[q][2] += pq * vv.z;
            acc[q][3] += pq * vv.w;
        }
    }
    for (int s = s_mid; s < s_end; s++) {
        if (((s - s_beg) & 1) != grp) continue;
        float4 vv = *(const float4*)(vdst + (size_t)s * DIM);
        #pragma unroll
        for (int q = 0; q < S_NEW; q++) {
            float pq = ps[q][s - s_beg];
            acc[q][0] += pq * vv.x;
            acc[q][1] += pq * vv.y;
            acc[q][2] += pq * vv.z;
            acc[q][3] += pq * vv.w;
        }
    }

    float* pbase = g_part + (size_t)(z * 2 + grp) * M_ROWS * DIM
                          + (size_t)b * S_NEW * DIM + col;
    #pragma unroll
    for (int q = 0; q < S_NEW; q++)
        *(float4*)(pbase + (size_t)q * DIM) = *(float4*)acc[q];
}

// ---------------------------------------------------------------------------
// Kernel 5: deterministic split-K combine for attention output.
// ---------------------------------------------------------------------------
__global__ void combine_kernel(float* __restrict__ out)
{
    const int idx = blockIdx.x * blockDim.x + threadIdx.x;
    const float4* p = (const float4*)g_part + idx;
    float4 a = {0.f, 0.f, 0.f, 0.f};
    #pragma unroll
    for (int z = 0; z < NSLICE; z++) {
        float4 v = p[(size_t)z * (M_ROWS * DIM / 4)];
        a.x += v.x; a.y += v.y; a.z += v.z; a.w += v.w;
    }
    ((float4*)out)[idx] = a;
}

// ---------------------------------------------------------------------------
extern "C" void kernel_launch(void* const* d_in, const int* in_sizes, int n_in,
                              void* d_out, int out_size)
{
    const float* input       = (const float*)d_in[0];
    const float* key_cache   = (const float*)d_in[1];
    const float* value_cache = (const float*)d_in[2];
    const float* Wk          = (const float*)d_in[3];
    const float* bk          = (const float*)d_in[4];
    const float* Wv          = (const float*)d_in[5];
    const float* bv          = (const float*)d_in[6];
    const float* Wq          = (const float*)d_in[7];
    const float* bq          = (const float*)d_in[8];

    float* out    = (float*)d_out;                                // [B, S_NEW, D]
    float* keys   = out + (size_t)BATCH * S_NEW * DIM;            // [B, S_TOT, D]
    float* values = keys + (size_t)BATCH * S_TOT * DIM;           // [B, S_TOT, D]

    // 1) split-K projections + combine (bias, routing to q / tails)   [0][1]
    proj_kernel<<<dim3(16, 4, 3 * KSPLIT), 256>>>(input, Wq, Wk, Wv);
    pcombine_kernel<<<768, 256>>>(bq, bk, bv, keys, values);

    // slot shim so scores_kernel is launch #3 (profiled slot)         [2]
    slot_kernel<<<1, 32>>>();

    // 2) fused key copy + scores                                      [3]
    scores_kernel<<<dim3(129, BATCH), 512>>>(key_cache, keys);

    // 3) softmax (register-resident)                                  [4]
    softmax_kernel<<<M_ROWS, 256>>>();

    // 4) fused value copy + split-K probs @ V                         [5]
    out_kernel<<<dim3(BATCH, SPLITS), 512>>>(value_cache, values);

    // 5) deterministic combine of split-K partials                    [6]
    combine_kernel<<<(M_ROWS * DIM / 4) / 256, 256>>>(out);
}

// round 17
// speedup vs baseline: 1.0466x; 1.0457x over previous
#include <cuda_runtime.h>
#include <cuda_bf16.h>
#include <math.h>

// Problem constants
#define BATCH   32
#define S_NEW   8
#define S_CACHE 4096
#define S_TOT   4104            // 4096 + 8
#define DIM     1024
#define M_ROWS  (BATCH * S_NEW) // 256
#define SPLITS  16
#define CHUNK   ((S_TOT + SPLITS - 1) / SPLITS)   // 257
#define NSLICE  (2 * SPLITS)                      // 32 partial slices
#define KSPLIT  4                                 // proj split-K factor

// Scratch (allocation-free rule: __device__ globals)
__device__ float g_q[M_ROWS * DIM];                   // 1 MB   q_new
__device__ float g_scores[M_ROWS * S_TOT];            // ~4.2 MB scores -> probs
__device__ float g_part[NSLICE * M_ROWS * DIM];       // 32 MB  split-K partials
__device__ float g_ppart[3 * KSPLIT * M_ROWS * DIM];  // 12.6 MB proj partials

// ---------------------------------------------------------------------------
// Kernel 1: split-K projections. Partial C for K chunk kc -> g_ppart.
// grid (16, 4, 12): blockIdx.z = z*KSPLIT + kc, z in {Q,K,V}.
// ---------------------------------------------------------------------------
__global__ void __launch_bounds__(256)
proj_kernel(const float* __restrict__ x,
            const float* __restrict__ Wq,
            const float* __restrict__ Wk,
            const float* __restrict__ Wv)
{
    const int z2 = blockIdx.z;
    const int z  = z2 >> 2;          // 0=Q,1=K,2=V
    const int kc = z2 & (KSPLIT - 1);
    const float* W = (z == 0) ? Wq : (z == 1) ? Wk : Wv;

    __shared__ float xs[64][17];
    __shared__ float ws[16][64];

    const int tid = threadIdx.x;
    const int tx = tid & 15, ty = tid >> 4;
    const int m0 = blockIdx.y * 64, n0 = blockIdx.x * 64;
    const int kbeg = kc * (DIM / KSPLIT), kend = kbeg + DIM / KSPLIT;

    float acc[4][4] = {};

    for (int k0 = kbeg; k0 < kend; k0 += 16) {
        {   // x tile 64x16
            int r = tid >> 2;
            int c = (tid & 3) * 4;
            float4 v = *(const float4*)(x + (size_t)(m0 + r) * DIM + k0 + c);
            xs[r][c] = v.x; xs[r][c + 1] = v.y; xs[r][c + 2] = v.z; xs[r][c + 3] = v.w;
        }
        {   // W tile 16x64
            int r = tid >> 4;
            int c = (tid & 15) * 4;
            *(float4*)&ws[r][c] = *(const float4*)(W + (size_t)(k0 + r) * DIM + n0 + c);
        }
        __syncthreads();
        #pragma unroll
        for (int kk = 0; kk < 16; kk++) {
            float a[4];
            #pragma unroll
            for (int i = 0; i < 4; i++) a[i] = xs[ty * 4 + i][kk];
            float4 bb = *(float4*)&ws[kk][tx * 4];
            #pragma unroll
            for (int i = 0; i < 4; i++) {
                acc[i][0] += a[i] * bb.x;
                acc[i][1] += a[i] * bb.y;
                acc[i][2] += a[i] * bb.z;
                acc[i][3] += a[i] * bb.w;
            }
        }
        __syncthreads();
    }

    float* dst = g_ppart + (size_t)z2 * M_ROWS * DIM;
    #pragma unroll
    for (int i = 0; i < 4; i++) {
        int m = m0 + ty * 4 + i;
        float4 v;
        v.x = acc[i][0]; v.y = acc[i][1]; v.z = acc[i][2]; v.w = acc[i][3];
        *(float4*)(dst + (size_t)m * DIM + n0 + tx * 4) = v;
    }
}

// ---------------------------------------------------------------------------
// Kernel 1b: proj combine. Sums KSPLIT partials + bias; routes to
// g_q (z=0) or keys/values tails (z=1,2). grid 768 x 256 (float4 jobs).
// ---------------------------------------------------------------------------
__global__ void __launch_bounds__(256)
pcombine_kernel(const float* __restrict__ bq,
                const float* __restrict__ bk,
                const float* __restrict__ bv,
                float* __restrict__ keys, float* __restrict__ values)
{
    const int idx = blockIdx.x * 256 + threadIdx.x;    // float4 job
    const int z   = idx >> 16;                          // 65536 f4 per z
    const int r   = idx & 65535;
    const int m   = r >> 8;
    const int n   = (r & 255) * 4;

    const float4* p = (const float4*)(g_ppart + (size_t)z * KSPLIT * M_ROWS * DIM
                                      + (size_t)m * DIM + n);
    float4 a = {0.f, 0.f, 0.f, 0.f};
    #pragma unroll
    for (int kc = 0; kc < KSPLIT; kc++) {
        float4 v = p[(size_t)kc * (M_ROWS * DIM / 4)];
        a.x += v.x; a.y += v.y; a.z += v.z; a.w += v.w;
    }
    const float* bias = (z == 0) ? bq : (z == 1) ? bk : bv;
    float4 bb = *(const float4*)(bias + n);
    a.x += bb.x; a.y += bb.y; a.z += bb.z; a.w += bb.w;

    if (z == 0) {
        *(float4*)(g_q + (size_t)m * DIM + n) = a;
    } else {
        int b = m >> 3, s = m & 7;
        float* dst = (z == 1) ? keys : values;
        *(float4*)(dst + (size_t)b * S_TOT * DIM + (size_t)(S_CACHE + s) * DIM + n) = a;
    }
}

// ---------------------------------------------------------------------------
// Dummy kernel: keeps scores_kernel at the profiled launch index.
// ---------------------------------------------------------------------------
__global__ void slot_kernel() {}

// ---------------------------------------------------------------------------
// Kernel 2: fused key-cache copy + scores (v6: 4 rows/warp, L1-traffic-first).
// 256 thr = 8 warps x 4 rows = 32 rows/block. q smem loads amortized over
// 4 rows -> LDS traffic halved vs v5. __launch_bounds__(256, 4): <=64 regs,
// 4 CTAs/SM = 32 warps (50% occ).
// grid (129, BATCH); blocks 0..127 cache rows, block 128 tail rows.
// ---------------------------------------------------------------------------
__global__ void __launch_bounds__(256, 4)
scores_kernel(const float* __restrict__ key_cache,
              float* __restrict__ keys)
{
    const int b    = blockIdx.y;
    const int tid  = threadIdx.x;
    const int warp = tid >> 5, lane = tid & 31;

    __shared__ float4 qs4[S_NEW * 256];   // 8 queries x 1024 floats = 32 KB
    {
        const float4* qsrc = (const float4*)(g_q + (size_t)b * S_NEW * DIM);
        #pragma unroll
        for (int i = 0; i < 8; i++) qs4[tid + i * 256] = qsrc[tid + i * 256];
    }
    __syncthreads();

    float acc[4][S_NEW] = {};
    int row0;

    if (blockIdx.x < 128) {
        row0 = blockIdx.x * 32 + warp * 4;
        const float4* src = (const float4*)(key_cache + ((size_t)b * S_CACHE + row0) * DIM) + lane;
        float4*       dst = (float4*)(keys + ((size_t)b * S_TOT + row0) * DIM) + lane;

        #pragma unroll
        for (int it = 0; it < 8; it++) {
            float4 a0 = __ldcs(src + it * 32);
            float4 a1 = __ldcs(src + it * 32 + 256);      // +DIM
            float4 a2 = __ldcs(src + it * 32 + 512);      // +2*DIM
            float4 a3 = __ldcs(src + it * 32 + 768);      // +3*DIM
            __stcs(dst + it * 32,       a0);
            __stcs(dst + it * 32 + 256, a1);
            __stcs(dst + it * 32 + 512, a2);
            __stcs(dst + it * 32 + 768, a3);
            #pragma unroll
            for (int q = 0; q < S_NEW; q++) {
                float4 qv = qs4[q * 256 + it * 32 + lane];
                acc[0][q] += a0.x * qv.x + a0.y * qv.y + a0.z * qv.z + a0.w * qv.w;
                acc[1][q] += a1.x * qv.x + a1.y * qv.y + a1.z * qv.z + a1.w * qv.w;
                acc[2][q] += a2.x * qv.x + a2.y * qv.y + a2.z * qv.z + a2.w * qv.w;
                acc[3][q] += a3.x * qv.x + a3.y * qv.y + a3.z * qv.z + a3.w * qv.w;
            }
        }
    } else {
        if (warp >= 2) return;
        row0 = S_CACHE + warp * 4;
        const float4* src = (const float4*)(keys + ((size_t)b * S_TOT + row0) * DIM) + lane;
        #pragma unroll
        for (int it = 0; it < 8; it++) {
            float4 a0 = *(src + it * 32);
            float4 a1 = *(src + it * 32 + 256);
            float4 a2 = *(src + it * 32 + 512);
            float4 a3 = *(src + it * 32 + 768);
            #pragma unroll
            for (int q = 0; q < S_NEW; q++) {
                float4 qv = qs4[q * 256 + it * 32 + lane];
                acc[0][q] += a0.x * qv.x + a0.y * qv.y + a0.z * qv.z + a0.w * qv.w;
                acc[1][q] += a1.x * qv.x + a1.y * qv.y + a1.z * qv.z + a1.w * qv.w;
                acc[2][q] += a2.x * qv.x + a2.y * qv.y + a2.z * qv.z + a2.w * qv.w;
                acc[3][q] += a3.x * qv.x + a3.y * qv.y + a3.z * qv.z + a3.w * qv.w;
            }
        }
    }

    #pragma unroll
    for (int r = 0; r < 4; r++) {
        #pragma unroll
        for (int q = 0; q < S_NEW; q++) {
            float v = acc[r][q];
            #pragma unroll
            for (int off = 16; off; off >>= 1)
                v += __shfl_down_sync(0xFFFFFFFFu, v, off);
            if (lane == 0)
                g_scores[((size_t)b * S_NEW + q) * S_TOT + row0 + r] = v * 0.03125f;
        }
    }
}

// ---------------------------------------------------------------------------
// Kernel 3: softmax, register-resident (1 read + 1 write per element).
// ---------------------------------------------------------------------------
#define SM_PER_T 17   // 256*17 = 4352 >= 4104
__global__ void __launch_bounds__(256)
softmax_kernel()
{
    float* p = g_scores + (size_t)blockIdx.x * S_TOT;
    const int tid = threadIdx.x;
    __shared__ float red[256];

    float val[SM_PER_T];
    float m = -1e30f;
    #pragma unroll
    for (int i = 0; i < SM_PER_T; i++) {
        int idx = tid + i * 256;
        val[i] = (idx < S_TOT) ? p[idx] : -1e30f;
        m = fmaxf(m, val[i]);
    }
    red[tid] = m; __syncthreads();
    for (int s = 128; s; s >>= 1) {
        if (tid < s) red[tid] = fmaxf(red[tid], red[tid + s]);
        __syncthreads();
    }
    m = red[0];
    __syncthreads();

    float sum = 0.f;
    #pragma unroll
    for (int i = 0; i < SM_PER_T; i++) {
        val[i] = __expf(val[i] - m);
        sum += val[i];
    }
    red[tid] = sum; __syncthreads();
    for (int s = 128; s; s >>= 1) {
        if (tid < s) red[tid] += red[tid + s];
        __syncthreads();
    }
    const float inv = 1.0f / red[0];
    #pragma unroll
    for (int i = 0; i < SM_PER_T; i++) {
        int idx = tid + i * 256;
        if (idx < S_TOT) p[idx] = val[i] * inv;
    }
}

// ---------------------------------------------------------------------------
// Kernel 4: fused value-cache copy + split-K probs @ V. (unchanged, 75% DRAM)
// ---------------------------------------------------------------------------
__global__ void __launch_bounds__(512)
out_kernel(const float* __restrict__ value_cache,
           float* __restrict__ values)
{
    const int b    = blockIdx.x;
    const int z    = blockIdx.y;
    const int tid  = threadIdx.x;
    const int grp  = tid >> 8;
    const int col  = (tid & 255) * 4;

    const int s_beg = z * CHUNK;
    const int s_end = (s_beg + CHUNK < S_TOT) ? s_beg + CHUNK : S_TOT;
    const int s_mid = (s_end < S_CACHE) ? s_end : ((s_beg > S_CACHE) ? s_beg : S_CACHE);

    __shared__ float ps[S_NEW][CHUNK];
    {
        const float* probs = g_scores + (size_t)b * S_NEW * S_TOT;
        const int n = s_end - s_beg;
        for (int i = tid; i < S_NEW * n; i += 512) {
            int q = i / n, s = i - q * n;
            ps[q][s] = probs[(size_t)q * S_TOT + s_beg + s];
        }
    }
    __syncthreads();

    float acc[S_NEW][4] = {};

    const float* vsrc = value_cache + (size_t)b * S_CACHE * DIM + col;
    float*       vdst = values      + (size_t)b * S_TOT   * DIM + col;

    #pragma unroll 2
    for (int s = s_beg + grp; s < s_mid; s += 2) {
        float4 vv = *(const float4*)(vsrc + (size_t)s * DIM);
        *(float4*)(vdst + (size_t)s * DIM) = vv;
        #pragma unroll
        for (int q = 0; q < S_NEW; q++) {
            float pq = ps[q][s - s_beg];
            acc[q][0] += pq * vv.x;
            acc[q][1] += pq * vv.y;
            acc[q][2] += pq * vv.z;
            acc[q][3] += pq * vv.w;
        }
    }
    for (int s = s_mid; s < s_end; s++) {
        if (((s - s_beg) & 1) != grp) continue;
        float4 vv = *(const float4*)(vdst + (size_t)s * DIM);
        #pragma unroll
        for (int q = 0; q < S_NEW; q++) {
            float pq = ps[q][s - s_beg];
            acc[q][0] += pq * vv.x;
            acc[q][1] += pq * vv.y;
            acc[q][2] += pq * vv.z;
            acc[q][3] += pq * vv.w;
        }
    }

    float* pbase = g_part + (size_t)(z * 2 + grp) * M_ROWS * DIM
                          + (size_t)b * S_NEW * DIM + col;
    #pragma unroll
    for (int q = 0; q < S_NEW; q++)
        *(float4*)(pbase + (size_t)q * DIM) = *(float4*)acc[q];
}

// ---------------------------------------------------------------------------
// Kernel 5: deterministic split-K combine for attention output.
// ---------------------------------------------------------------------------
__global__ void combine_kernel(float* __restrict__ out)
{
    const int idx = blockIdx.x * blockDim.x + threadIdx.x;
    const float4* p = (const float4*)g_part + idx;
    float4 a = {0.f, 0.f, 0.f, 0.f};
    #pragma unroll
    for (int z = 0; z < NSLICE; z++) {
        float4 v = p[(size_t)z * (M_ROWS * DIM / 4)];
        a.x += v.x; a.y += v.y; a.z += v.z; a.w += v.w;
    }
    ((float4*)out)[idx] = a;
}

// ---------------------------------------------------------------------------
extern "C" void kernel_launch(void* const* d_in, const int* in_sizes, int n_in,
                              void* d_out, int out_size)
{
    const float* input       = (const float*)d_in[0];
    const float* key_cache   = (const float*)d_in[1];
    const float* value_cache = (const float*)d_in[2];
    const float* Wk          = (const float*)d_in[3];
    const float* bk          = (const float*)d_in[4];
    const float* Wv          = (const float*)d_in[5];
    const float* bv          = (const float*)d_in[6];
    const float* Wq          = (const float*)d_in[7];
    const float* bq          = (const float*)d_in[8];

    float* out    = (float*)d_out;                                // [B, S_NEW, D]
    float* keys   = out + (size_t)BATCH * S_NEW * DIM;            // [B, S_TOT, D]
    float* values = keys + (size_t)BATCH * S_TOT * DIM;           // [B, S_TOT, D]

    // 1) split-K projections + combine (bias, routing to q / tails)   [0][1]
    proj_kernel<<<dim3(16, 4, 3 * KSPLIT), 256>>>(input, Wq, Wk, Wv);
    pcombine_kernel<<<768, 256>>>(bq, bk, bv, keys, values);

    // slot shim so scores_kernel is launch #3 (profiled slot)         [2]
    slot_kernel<<<1, 32>>>();

    // 2) fused key copy + scores (4 rows/warp, reg-capped)            [3]
    scores_kernel<<<dim3(129, BATCH), 256>>>(key_cache, keys);

    // 3) softmax (register-resident)                                  [4]
    softmax_kernel<<<M_ROWS, 256>>>();

    // 4) fused value copy + split-K probs @ V                         [5]
    out_kernel<<<dim3(BATCH, SPLITS), 512>>>(value_cache, values);

    // 5) deterministic combine of split-K partials                    [6]
    combine_kernel<<<(M_ROWS * DIM / 4) / 256, 256>>>(out);
}